// round 9
// baseline (speedup 1.0000x reference)
#include <cuda_runtime.h>
#include <math.h>
#include <stdint.h>

#define BATCH    32
#define NSRC     4
#define TLEN     64000
#define NSTAT    20
#define NPAIR    (BATCH * NSTAT)    // 640
#define NK       16
#define THREADS  256
#define NCONS    224                // consumer threads (warps 0-6)
#define CPB      9                  // chunks (blocks) per batch
#define NBLOCKS  (BATCH * CPB)      // 288 = 2 CTA/SM on 144 SMs
#define BF4      (TLEN / 4)         // 16000 float4 per stream per batch
#define CHUNK_F4 1778               // ceil(16000/9); last chunk = 1776

#define NSTAGES  5
#define TILE_F4  224                // one float4 per consumer thread per stream
#define TILE_B   (TILE_F4 * 16)     // 3584 bytes per stream
#define STREAMS  6
#define STAGE_B  (TILE_B * STREAMS) // 21504 bytes
#define MAXTILES ((CHUNK_F4 + TILE_F4 - 1) / TILE_F4)   // 8

// smem: [0..40) full mbars, [64..104) empty mbars, data at 1024
#define SM_FULL(s)  ((s) * 8)
#define SM_EMPTY(s) (64 + (s) * 8)
#define SM_DATA     1024
#define SMEM_TOTAL  (SM_DATA + NSTAGES * STAGE_B)   // 108544 -> 2 CTA/SM

__device__ float g_partials[NPAIR * CPB];
__device__ int   g_count = 0;

__device__ __forceinline__ uint32_t smem_u32(const void* p) {
    uint32_t a;
    asm("{ .reg .u64 t; cvta.to.shared.u64 t, %1; cvt.u32.u64 %0, t; }" : "=r"(a) : "l"(p));
    return a;
}
__device__ __forceinline__ void mbar_init(uint32_t m, uint32_t cnt) {
    asm volatile("mbarrier.init.shared.b64 [%0], %1;" :: "r"(m), "r"(cnt) : "memory");
}
__device__ __forceinline__ void mbar_arrive(uint32_t m) {
    asm volatile("mbarrier.arrive.shared.b64 _, [%0];" :: "r"(m) : "memory");
}
__device__ __forceinline__ void mbar_expect_tx(uint32_t m, uint32_t bytes) {
    asm volatile("mbarrier.arrive.expect_tx.shared.b64 _, [%0], %1;" :: "r"(m), "r"(bytes) : "memory");
}
__device__ __forceinline__ void mbar_wait(uint32_t m, uint32_t parity) {
    asm volatile(
        "{\n\t.reg .pred P;\n\t"
        "W_%=:\n\t"
        "mbarrier.try_wait.parity.acquire.cta.shared::cta.b64 P, [%0], %1, 0x989680;\n\t"
        "@P bra D_%=;\n\t"
        "bra W_%=;\n\t"
        "D_%=:\n\t}"
        :: "r"(m), "r"(parity) : "memory");
}
__device__ __forceinline__ void bulk_g2s(uint32_t dst, const void* src, uint32_t bytes, uint32_t mbar) {
    asm volatile(
        "cp.async.bulk.shared::cluster.global.mbarrier::complete_tx::bytes [%0], [%1], %2, [%3];"
        :: "r"(dst), "l"(src), "r"(bytes), "r"(mbar) : "memory");
}

// stat layout: 0..9 Gram UT (00,01,02,03,11,12,13,22,23,33); 10..13 P1; 14..17 P2; 18 |m1|^2; 19 |m2|^2
__device__ __forceinline__ void accum6(float* __restrict__ acc,
                                       float4 a0, float4 a1, float4 a2, float4 a3,
                                       float4 v1, float4 v2)
{
#define LANE(C) do {                                                       \
    float x0 = a0.C, x1 = a1.C, x2 = a2.C, x3 = a3.C;                      \
    float y1 = v1.C, y2 = v2.C;                                            \
    acc[0]  = fmaf(x0, x0, acc[0]);                                        \
    acc[1]  = fmaf(x0, x1, acc[1]);                                        \
    acc[2]  = fmaf(x0, x2, acc[2]);                                        \
    acc[3]  = fmaf(x0, x3, acc[3]);                                        \
    acc[4]  = fmaf(x1, x1, acc[4]);                                        \
    acc[5]  = fmaf(x1, x2, acc[5]);                                        \
    acc[6]  = fmaf(x1, x3, acc[6]);                                        \
    acc[7]  = fmaf(x2, x2, acc[7]);                                        \
    acc[8]  = fmaf(x2, x3, acc[8]);                                        \
    acc[9]  = fmaf(x3, x3, acc[9]);                                        \
    acc[10] = fmaf(x0, y1, acc[10]);                                       \
    acc[11] = fmaf(x1, y1, acc[11]);                                       \
    acc[12] = fmaf(x2, y1, acc[12]);                                       \
    acc[13] = fmaf(x3, y1, acc[13]);                                       \
    acc[14] = fmaf(x0, y2, acc[14]);                                       \
    acc[15] = fmaf(x1, y2, acc[15]);                                       \
    acc[16] = fmaf(x2, y2, acc[16]);                                       \
    acc[17] = fmaf(x3, y2, acc[17]);                                       \
    acc[18] = fmaf(y1, y1, acc[18]);                                       \
    acc[19] = fmaf(y2, y2, acc[19]);                                       \
} while (0)
    LANE(x); LANE(y); LANE(z); LANE(w);
#undef LANE
}

__device__ __forceinline__ float mixit_loss(int k, const float* __restrict__ st)
{
    float m[NSRC], mc[NSRC];
#pragma unroll
    for (int s = 0; s < NSRC; s++) {
        m[s]  = (float)((k >> (3 - s)) & 1);   // itertools.product: last varies fastest
        mc[s] = 1.0f - m[s];
    }
    const int gi[4][4] = {{0,1,2,3},{1,4,5,6},{2,5,7,8},{3,6,8,9}};
    float q0 = 0.0f, q1 = 0.0f, c0 = 0.0f, c1 = 0.0f;
#pragma unroll
    for (int s = 0; s < NSRC; s++) {
#pragma unroll
        for (int s2 = 0; s2 < NSRC; s2++) {
            float g = st[gi[s][s2]];
            q0 = fmaf(m[s]  * m[s2],  g, q0);
            q1 = fmaf(mc[s] * mc[s2], g, q1);
        }
        c0 = fmaf(m[s],  st[10 + s], c0);
        c1 = fmaf(mc[s], st[14 + s], c1);
    }
    const float a0 = q0 - 2.0f * c0 + st[18];
    const float a1 = q1 - 2.0f * c1 + st[19];
    return 10.0f * (__log10f(fmaf(30.0f, q0, a0)) - __log10f(q0)) +
           10.0f * (__log10f(fmaf(30.0f, q1, a1)) - __log10f(q1));
}

__global__ __launch_bounds__(THREADS)
void mixit_kernel(const float* __restrict__ est,
                  const float* __restrict__ m1,
                  const float* __restrict__ m2,
                  float* __restrict__ out, int out_size)
{
    extern __shared__ char smem[];
    const uint32_t sb = smem_u32(smem);
    const int tid = threadIdx.x;
    const int wid = tid >> 5;
    const int blk = blockIdx.x;            // b * CPB + q
    const int b   = blk / CPB;
    const int q   = blk % CPB;

    const int start  = q * CHUNK_F4;
    const int end    = (start + CHUNK_F4 < BF4) ? (start + CHUNK_F4) : BF4;
    const int nf4    = end - start;                        // 1778 or 1776
    const int ntiles = (nf4 + TILE_F4 - 1) / TILE_F4;      // 8

    const float* srcs[STREAMS];
#pragma unroll
    for (int s = 0; s < NSRC; s++)
        srcs[s] = est + (size_t)b * NSRC * TLEN + (size_t)s * TLEN + (size_t)start * 4;
    srcs[4] = m1 + (size_t)b * TLEN + (size_t)start * 4;
    srcs[5] = m2 + (size_t)b * TLEN + (size_t)start * 4;

    if (tid == 0) {
#pragma unroll
        for (int s = 0; s < NSTAGES; s++) {
            mbar_init(sb + SM_FULL(s), 1);       // producer expect_tx arrives once
            mbar_init(sb + SM_EMPTY(s), NCONS);  // 224 consumers arrive
        }
    }
    __syncthreads();

    float acc[NSTAT];
#pragma unroll
    for (int i = 0; i < NSTAT; i++) acc[i] = 0.0f;

    if (wid == 7) {
        // ---------------- producer warp (lane 0 only issues) ----------------
        if ((tid & 31) == 0) {
            for (int t = 0; t < ntiles; t++) {
                const int stage = t % NSTAGES;
                if (t >= NSTAGES)
                    mbar_wait(sb + SM_EMPTY(stage), (t / NSTAGES - 1) & 1);
                const int tf4 = (t == ntiles - 1) ? (nf4 - t * TILE_F4) : TILE_F4;
                const uint32_t bytes = (uint32_t)tf4 * 16u;
                const uint32_t mb = sb + SM_FULL(stage);
                mbar_expect_tx(mb, bytes * STREAMS);
#pragma unroll
                for (int j = 0; j < STREAMS; j++)
                    bulk_g2s(sb + SM_DATA + stage * STAGE_B + j * TILE_B,
                             srcs[j] + (size_t)t * TILE_F4 * 4, bytes, mb);
            }
        }
        // producer warp contributes zero acc; falls through to reduction
    } else {
        // ---------------- consumer warps 0-6 (224 threads) ------------------
        for (int t = 0; t < ntiles; t++) {
            const int stage = t % NSTAGES;
            mbar_wait(sb + SM_FULL(stage), (t / NSTAGES) & 1);

            const int tf4 = (t == ntiles - 1) ? (nf4 - t * TILE_F4) : TILE_F4;
            if (tid < tf4) {
                const char* base = smem + SM_DATA + stage * STAGE_B;
                const float4 a0 = *(const float4*)(base + 0 * TILE_B + tid * 16);
                const float4 a1 = *(const float4*)(base + 1 * TILE_B + tid * 16);
                const float4 a2 = *(const float4*)(base + 2 * TILE_B + tid * 16);
                const float4 a3 = *(const float4*)(base + 3 * TILE_B + tid * 16);
                const float4 v1 = *(const float4*)(base + 4 * TILE_B + tid * 16);
                const float4 v2 = *(const float4*)(base + 5 * TILE_B + tid * 16);
                accum6(acc, a0, a1, a2, a3, v1, v2);
            }
            // all loads above feed FMAs before this point in program order,
            // so their data is in registers before the arrive can issue.
            mbar_arrive(sb + SM_EMPTY(stage));
        }
    }

    // block reduction of the 20 stats (producer warp adds zeros)
#pragma unroll
    for (int st = 0; st < NSTAT; st++) {
        float v = acc[st];
        v += __shfl_down_sync(0xffffffffu, v, 16);
        v += __shfl_down_sync(0xffffffffu, v, 8);
        v += __shfl_down_sync(0xffffffffu, v, 4);
        v += __shfl_down_sync(0xffffffffu, v, 2);
        v += __shfl_down_sync(0xffffffffu, v, 1);
        acc[st] = v;
    }
    __shared__ float sred[THREADS / 32][NSTAT];
    const int lane = tid & 31;
    if (lane == 0) {
#pragma unroll
        for (int st = 0; st < NSTAT; st++) sred[wid][st] = acc[st];
    }
    __syncthreads();
    if (tid < NSTAT) {
        float s = 0.0f;
#pragma unroll
        for (int w = 0; w < THREADS / 32; w++) s += sred[w][tid];
        g_partials[(b * NSTAT + tid) * CPB + q] = s;
    }

    // ---- last-block epilogue -------------------------------------------
    __shared__ int s_last;
    __threadfence();
    if (tid == 0) {
        int old = atomicAdd(&g_count, 1);
        s_last = (old == NBLOCKS - 1) ? 1 : 0;
    }
    __syncthreads();
    if (!s_last) return;
    __threadfence();

    __shared__ float sstats[NPAIR];
    __shared__ float ksum[NK];

    for (int p = tid; p < NPAIR; p += THREADS) {
        const float* row = g_partials + p * CPB;
        float s = 0.0f;
#pragma unroll
        for (int c = 0; c < CPB; c++) s += row[c];
        sstats[p] = s;
    }
    __syncthreads();

    {
        const int w  = tid >> 5;
        const int bb = tid & 31;
        const float* st = &sstats[bb * NSTAT];
        float l0 = mixit_loss(w,     st);
        float l1 = mixit_loss(w + 8, st);
#pragma unroll
        for (int off = 16; off > 0; off >>= 1) {
            l0 += __shfl_down_sync(0xffffffffu, l0, off);
            l1 += __shfl_down_sync(0xffffffffu, l1, off);
        }
        if (bb == 0) { ksum[w] = l0; ksum[w + 8] = l1; }
    }
    __syncthreads();

    if (tid == 0) {
        float best = ksum[0];
        int bi = 0;
#pragma unroll
        for (int kk = 1; kk < NK; kk++) {
            float v = ksum[kk];
            if (v < best) { best = v; bi = kk; }   // first occurrence wins (jnp.argmin)
        }
        out[0] = (float)bi;
        if (out_size > 1) out[1] = best;
        g_count = 0;
    }
}

extern "C" void kernel_launch(void* const* d_in, const int* in_sizes, int n_in,
                              void* d_out, int out_size)
{
    const float* est = (const float*)d_in[0];   // [32, 4, 64000]
    const float* m1  = (const float*)d_in[1];   // [32, 64000]
    const float* m2  = (const float*)d_in[2];   // [32, 64000]

    cudaFuncSetAttribute(mixit_kernel, cudaFuncAttributeMaxDynamicSharedMemorySize, SMEM_TOTAL);
    mixit_kernel<<<NBLOCKS, THREADS, SMEM_TOTAL>>>(est, m1, m2, (float*)d_out, out_size);
}

// round 10
// speedup vs baseline: 1.3589x; 1.3589x over previous
#include <cuda_runtime.h>
#include <math.h>

#define BATCH    32
#define NSRC     4
#define TLEN     64000
#define NSTAT    20
#define NPAIR    (BATCH * NSTAT)    // 640
#define NK       16
#define THREADS  128
#define CPB      37                 // chunks (blocks) per batch
#define NBLOCKS  (BATCH * CPB)      // 1184 = 148 SMs x 8 CTAs: one perfect wave
#define BF4      (TLEN / 4)         // 16000 float4 per stream per batch
#define CHUNK_F4 433                // ceil(16000/37); last chunk = 412

// Partials: [pair][chunk], pair = b*NSTAT+st.
__device__ float g_partials[NPAIR * CPB];
__device__ int   g_count = 0;

// stat layout: 0..9 Gram UT (00,01,02,03,11,12,13,22,23,33); 10..13 P1; 14..17 P2; 18 |m1|^2; 19 |m2|^2
__device__ __forceinline__ float mixit_loss(int k, const float* __restrict__ st)
{
    float m[NSRC], mc[NSRC];
#pragma unroll
    for (int s = 0; s < NSRC; s++) {
        m[s]  = (float)((k >> (3 - s)) & 1);   // itertools.product: last varies fastest
        mc[s] = 1.0f - m[s];
    }
    const int gi[4][4] = {{0,1,2,3},{1,4,5,6},{2,5,7,8},{3,6,8,9}};
    float q0 = 0.0f, q1 = 0.0f, c0 = 0.0f, c1 = 0.0f;
#pragma unroll
    for (int s = 0; s < NSRC; s++) {
#pragma unroll
        for (int s2 = 0; s2 < NSRC; s2++) {
            float g = st[gi[s][s2]];
            q0 = fmaf(m[s]  * m[s2],  g, q0);
            q1 = fmaf(mc[s] * mc[s2], g, q1);
        }
        c0 = fmaf(m[s],  st[10 + s], c0);
        c1 = fmaf(mc[s], st[14 + s], c1);
    }
    const float a0 = q0 - 2.0f * c0 + st[18];
    const float a1 = q1 - 2.0f * c1 + st[19];
    return 10.0f * (__log10f(fmaf(30.0f, q0, a0)) - __log10f(q0)) +
           10.0f * (__log10f(fmaf(30.0f, q1, a1)) - __log10f(q1));
}

__global__ __launch_bounds__(THREADS, 8)
void mixit_kernel(const float* __restrict__ est,
                  const float* __restrict__ m1,
                  const float* __restrict__ m2,
                  float* __restrict__ out, int out_size)
{
    const int tid = threadIdx.x;
    const int blk = blockIdx.x;            // b * CPB + q
    const int b   = blk / CPB;
    const int q   = blk % CPB;

    const int start = q * CHUNK_F4;
    const int end   = (start + CHUNK_F4 < BF4) ? (start + CHUNK_F4) : BF4;

    const float4* e0 = (const float4*)(est + (size_t)b * NSRC * TLEN + 0 * (size_t)TLEN);
    const float4* e1 = (const float4*)(est + (size_t)b * NSRC * TLEN + 1 * (size_t)TLEN);
    const float4* e2 = (const float4*)(est + (size_t)b * NSRC * TLEN + 2 * (size_t)TLEN);
    const float4* e3 = (const float4*)(est + (size_t)b * NSRC * TLEN + 3 * (size_t)TLEN);
    const float4* p1 = (const float4*)(m1 + (size_t)b * TLEN);
    const float4* p2 = (const float4*)(m2 + (size_t)b * TLEN);

    float acc[NSTAT];
#pragma unroll
    for (int i = 0; i < NSTAT; i++) acc[i] = 0.0f;

    for (int i = start + tid; i < end; i += THREADS) {
        float4 a0 = e0[i];
        float4 a1 = e1[i];
        float4 a2 = e2[i];
        float4 a3 = e3[i];
        float4 v1 = p1[i];
        float4 v2 = p2[i];

#define LANE(C) do {                                                       \
        float x0 = a0.C, x1 = a1.C, x2 = a2.C, x3 = a3.C;                  \
        float y1 = v1.C, y2 = v2.C;                                        \
        acc[0]  = fmaf(x0, x0, acc[0]);                                    \
        acc[1]  = fmaf(x0, x1, acc[1]);                                    \
        acc[2]  = fmaf(x0, x2, acc[2]);                                    \
        acc[3]  = fmaf(x0, x3, acc[3]);                                    \
        acc[4]  = fmaf(x1, x1, acc[4]);                                    \
        acc[5]  = fmaf(x1, x2, acc[5]);                                    \
        acc[6]  = fmaf(x1, x3, acc[6]);                                    \
        acc[7]  = fmaf(x2, x2, acc[7]);                                    \
        acc[8]  = fmaf(x2, x3, acc[8]);                                    \
        acc[9]  = fmaf(x3, x3, acc[9]);                                    \
        acc[10] = fmaf(x0, y1, acc[10]);                                   \
        acc[11] = fmaf(x1, y1, acc[11]);                                   \
        acc[12] = fmaf(x2, y1, acc[12]);                                   \
        acc[13] = fmaf(x3, y1, acc[13]);                                   \
        acc[14] = fmaf(x0, y2, acc[14]);                                   \
        acc[15] = fmaf(x1, y2, acc[15]);                                   \
        acc[16] = fmaf(x2, y2, acc[16]);                                   \
        acc[17] = fmaf(x3, y2, acc[17]);                                   \
        acc[18] = fmaf(y1, y1, acc[18]);                                   \
        acc[19] = fmaf(y2, y2, acc[19]);                                   \
    } while (0)

        LANE(x); LANE(y); LANE(z); LANE(w);
#undef LANE
    }

    // block reduction of the 20 stats (4 warps)
#pragma unroll
    for (int st = 0; st < NSTAT; st++) {
        float v = acc[st];
        v += __shfl_down_sync(0xffffffffu, v, 16);
        v += __shfl_down_sync(0xffffffffu, v, 8);
        v += __shfl_down_sync(0xffffffffu, v, 4);
        v += __shfl_down_sync(0xffffffffu, v, 2);
        v += __shfl_down_sync(0xffffffffu, v, 1);
        acc[st] = v;
    }
    __shared__ float sred[THREADS / 32][NSTAT];
    const int warp = tid >> 5;
    const int lane = tid & 31;
    if (lane == 0) {
#pragma unroll
        for (int st = 0; st < NSTAT; st++) sred[warp][st] = acc[st];
    }
    __syncthreads();
    if (tid < NSTAT) {
        float s = 0.0f;
#pragma unroll
        for (int w = 0; w < THREADS / 32; w++) s += sred[w][tid];
        g_partials[(b * NSTAT + tid) * CPB + q] = s;
    }

    // ---- last-block epilogue -------------------------------------------
    __shared__ int s_last;
    __threadfence();
    if (tid == 0) {
        int old = atomicAdd(&g_count, 1);
        s_last = (old == NBLOCKS - 1) ? 1 : 0;
    }
    __syncthreads();
    if (!s_last) return;
    __threadfence();

    __shared__ float sstats[NPAIR];
    __shared__ float ksum[NK];

    // 640 pairs / 128 threads: 37 contiguous scalar adds per pair, fixed order.
    for (int p = tid; p < NPAIR; p += THREADS) {
        const float* row = g_partials + p * CPB;
        float s = 0.0f;
#pragma unroll
        for (int c = 0; c < CPB; c++) s += row[c];
        sstats[p] = s;
    }
    __syncthreads();

    // 4 warps; warp w handles k = w, w+4, w+8, w+12; lane = batch index.
    {
        const int w  = tid >> 5;
        const int bb = tid & 31;
        const float* st = &sstats[bb * NSTAT];
        float l0 = mixit_loss(w,      st);
        float l1 = mixit_loss(w + 4,  st);
        float l2 = mixit_loss(w + 8,  st);
        float l3 = mixit_loss(w + 12, st);
#pragma unroll
        for (int off = 16; off > 0; off >>= 1) {
            l0 += __shfl_down_sync(0xffffffffu, l0, off);
            l1 += __shfl_down_sync(0xffffffffu, l1, off);
            l2 += __shfl_down_sync(0xffffffffu, l2, off);
            l3 += __shfl_down_sync(0xffffffffu, l3, off);
        }
        if (bb == 0) {
            ksum[w]      = l0;
            ksum[w + 4]  = l1;
            ksum[w + 8]  = l2;
            ksum[w + 12] = l3;
        }
    }
    __syncthreads();

    if (tid == 0) {
        float best = ksum[0];
        int bi = 0;
#pragma unroll
        for (int kk = 1; kk < NK; kk++) {
            float v = ksum[kk];
            if (v < best) { best = v; bi = kk; }   // first occurrence wins (jnp.argmin)
        }
        out[0] = (float)bi;
        if (out_size > 1) out[1] = best;
        g_count = 0;
    }
}

extern "C" void kernel_launch(void* const* d_in, const int* in_sizes, int n_in,
                              void* d_out, int out_size)
{
    const float* est = (const float*)d_in[0];   // [32, 4, 64000]
    const float* m1  = (const float*)d_in[1];   // [32, 64000]
    const float* m2  = (const float*)d_in[2];   // [32, 64000]

    mixit_kernel<<<NBLOCKS, THREADS>>>(est, m1, m2, (float*)d_out, out_size);
}

// round 11
// speedup vs baseline: 1.5668x; 1.1530x over previous
#include <cuda_runtime.h>
#include <math.h>

#define BATCH    32
#define NSRC     4
#define TLEN     64000
#define NSTAT    20
#define NPAIR    (BATCH * NSTAT)    // 640
#define NK       16
#define THREADS  256
#define BF4      (TLEN / 4)         // 16000 float4 per stream per batch
#define CPB_HI   19                 // chunks per batch, batches 0..15
#define CPB_LO   18                 // chunks per batch, batches 16..31
#define NBLK_HI  (16 * CPB_HI)      // 304
#define NBLOCKS  (NBLK_HI + 16 * CPB_LO)   // 592 = 148 SMs x 4 CTAs exactly
#define MAXCPB   CPB_HI             // partials padded to 19 slots

// Partials: [pair][chunk-slot(19)], pair = b*NSTAT+st. Slot 18 for b>=16 is
// never written; __device__ globals are zero-initialized, so summing all 19
// slots is always exact and replay-safe.
__device__ float g_partials[NPAIR * MAXCPB];
__device__ int   g_count = 0;

// stat layout: 0..9 Gram UT (00,01,02,03,11,12,13,22,23,33); 10..13 P1; 14..17 P2; 18 |m1|^2; 19 |m2|^2
__device__ __forceinline__ float mixit_loss(int k, const float* __restrict__ st)
{
    float m[NSRC], mc[NSRC];
#pragma unroll
    for (int s = 0; s < NSRC; s++) {
        m[s]  = (float)((k >> (3 - s)) & 1);   // itertools.product: last varies fastest
        mc[s] = 1.0f - m[s];
    }
    const int gi[4][4] = {{0,1,2,3},{1,4,5,6},{2,5,7,8},{3,6,8,9}};
    float q0 = 0.0f, q1 = 0.0f, c0 = 0.0f, c1 = 0.0f;
#pragma unroll
    for (int s = 0; s < NSRC; s++) {
#pragma unroll
        for (int s2 = 0; s2 < NSRC; s2++) {
            float g = st[gi[s][s2]];
            q0 = fmaf(m[s]  * m[s2],  g, q0);
            q1 = fmaf(mc[s] * mc[s2], g, q1);
        }
        c0 = fmaf(m[s],  st[10 + s], c0);
        c1 = fmaf(mc[s], st[14 + s], c1);
    }
    const float a0 = q0 - 2.0f * c0 + st[18];
    const float a1 = q1 - 2.0f * c1 + st[19];
    return 10.0f * (__log10f(fmaf(30.0f, q0, a0)) - __log10f(q0)) +
           10.0f * (__log10f(fmaf(30.0f, q1, a1)) - __log10f(q1));
}

__global__ __launch_bounds__(THREADS, 4)
void mixit_kernel(const float* __restrict__ est,
                  const float* __restrict__ m1,
                  const float* __restrict__ m2,
                  float* __restrict__ out, int out_size)
{
    const int tid = threadIdx.x;
    const int blk = blockIdx.x;

    // blk -> (batch b, chunk q, nchunks)
    int b, q, nchunks;
    if (blk < NBLK_HI) { b = blk / CPB_HI;        q = blk % CPB_HI;        nchunks = CPB_HI; }
    else               { int r = blk - NBLK_HI;
                         b = 16 + r / CPB_LO;     q = r % CPB_LO;          nchunks = CPB_LO; }

    const int start = (q * BF4) / nchunks;
    const int end   = ((q + 1) * BF4) / nchunks;

    const float4* e0 = (const float4*)(est + (size_t)b * NSRC * TLEN + 0 * (size_t)TLEN);
    const float4* e1 = (const float4*)(est + (size_t)b * NSRC * TLEN + 1 * (size_t)TLEN);
    const float4* e2 = (const float4*)(est + (size_t)b * NSRC * TLEN + 2 * (size_t)TLEN);
    const float4* e3 = (const float4*)(est + (size_t)b * NSRC * TLEN + 3 * (size_t)TLEN);
    const float4* p1 = (const float4*)(m1 + (size_t)b * TLEN);
    const float4* p2 = (const float4*)(m2 + (size_t)b * TLEN);

    float acc[NSTAT];
#pragma unroll
    for (int i = 0; i < NSTAT; i++) acc[i] = 0.0f;

#pragma unroll 2
    for (int i = start + tid; i < end; i += THREADS) {
        float4 a0 = e0[i];
        float4 a1 = e1[i];
        float4 a2 = e2[i];
        float4 a3 = e3[i];
        float4 v1 = p1[i];
        float4 v2 = p2[i];

#define LANE(C) do {                                                       \
        float x0 = a0.C, x1 = a1.C, x2 = a2.C, x3 = a3.C;                  \
        float y1 = v1.C, y2 = v2.C;                                        \
        acc[0]  = fmaf(x0, x0, acc[0]);                                    \
        acc[1]  = fmaf(x0, x1, acc[1]);                                    \
        acc[2]  = fmaf(x0, x2, acc[2]);                                    \
        acc[3]  = fmaf(x0, x3, acc[3]);                                    \
        acc[4]  = fmaf(x1, x1, acc[4]);                                    \
        acc[5]  = fmaf(x1, x2, acc[5]);                                    \
        acc[6]  = fmaf(x1, x3, acc[6]);                                    \
        acc[7]  = fmaf(x2, x2, acc[7]);                                    \
        acc[8]  = fmaf(x2, x3, acc[8]);                                    \
        acc[9]  = fmaf(x3, x3, acc[9]);                                    \
        acc[10] = fmaf(x0, y1, acc[10]);                                   \
        acc[11] = fmaf(x1, y1, acc[11]);                                   \
        acc[12] = fmaf(x2, y1, acc[12]);                                   \
        acc[13] = fmaf(x3, y1, acc[13]);                                   \
        acc[14] = fmaf(x0, y2, acc[14]);                                   \
        acc[15] = fmaf(x1, y2, acc[15]);                                   \
        acc[16] = fmaf(x2, y2, acc[16]);                                   \
        acc[17] = fmaf(x3, y2, acc[17]);                                   \
        acc[18] = fmaf(y1, y1, acc[18]);                                   \
        acc[19] = fmaf(y2, y2, acc[19]);                                   \
    } while (0)

        LANE(x); LANE(y); LANE(z); LANE(w);
#undef LANE
    }

    // block reduction of the 20 stats
#pragma unroll
    for (int st = 0; st < NSTAT; st++) {
        float v = acc[st];
        v += __shfl_down_sync(0xffffffffu, v, 16);
        v += __shfl_down_sync(0xffffffffu, v, 8);
        v += __shfl_down_sync(0xffffffffu, v, 4);
        v += __shfl_down_sync(0xffffffffu, v, 2);
        v += __shfl_down_sync(0xffffffffu, v, 1);
        acc[st] = v;
    }
    __shared__ float sred[THREADS / 32][NSTAT];
    const int warp = tid >> 5;
    const int lane = tid & 31;
    if (lane == 0) {
#pragma unroll
        for (int st = 0; st < NSTAT; st++) sred[warp][st] = acc[st];
    }
    __syncthreads();
    if (tid < NSTAT) {
        float s = 0.0f;
#pragma unroll
        for (int w = 0; w < THREADS / 32; w++) s += sred[w][tid];
        g_partials[(b * NSTAT + tid) * MAXCPB + q] = s;
    }

    // ---- last-block epilogue -------------------------------------------
    __shared__ int s_last;
    __threadfence();
    if (tid == 0) {
        int old = atomicAdd(&g_count, 1);
        s_last = (old == NBLOCKS - 1) ? 1 : 0;
    }
    __syncthreads();
    if (!s_last) return;
    __threadfence();

    __shared__ float sstats[NPAIR];
    __shared__ float ksum[NK];

    // 640 pairs / 256 threads: 19 contiguous scalar adds per pair, fixed order.
    // (slot 18 of b>=16 is always 0.0f -> exact)
    for (int p = tid; p < NPAIR; p += THREADS) {
        const float* row = g_partials + p * MAXCPB;
        float s = 0.0f;
#pragma unroll
        for (int c = 0; c < MAXCPB; c++) s += row[c];
        sstats[p] = s;
    }
    __syncthreads();

    // 8 warps; warp w handles k = w and k = w+8; lane = batch index.
    {
        const int w  = tid >> 5;
        const int bb = tid & 31;
        const float* st = &sstats[bb * NSTAT];
        float l0 = mixit_loss(w,     st);
        float l1 = mixit_loss(w + 8, st);
#pragma unroll
        for (int off = 16; off > 0; off >>= 1) {
            l0 += __shfl_down_sync(0xffffffffu, l0, off);
            l1 += __shfl_down_sync(0xffffffffu, l1, off);
        }
        if (bb == 0) { ksum[w] = l0; ksum[w + 8] = l1; }
    }
    __syncthreads();

    if (tid == 0) {
        float best = ksum[0];
        int bi = 0;
#pragma unroll
        for (int kk = 1; kk < NK; kk++) {
            float v = ksum[kk];
            if (v < best) { best = v; bi = kk; }   // first occurrence wins (jnp.argmin)
        }
        out[0] = (float)bi;
        if (out_size > 1) out[1] = best;
        g_count = 0;
    }
}

extern "C" void kernel_launch(void* const* d_in, const int* in_sizes, int n_in,
                              void* d_out, int out_size)
{
    const float* est = (const float*)d_in[0];   // [32, 4, 64000]
    const float* m1  = (const float*)d_in[1];   // [32, 64000]
    const float* m2  = (const float*)d_in[2];   // [32, 64000]

    mixit_kernel<<<NBLOCKS, THREADS>>>(est, m1, m2, (float*)d_out, out_size);
}